// round 8
// baseline (speedup 1.0000x reference)
#include <cuda_runtime.h>
#include <cuda_bf16.h>
#include <cfloat>
#include <cstdint>

#define E_DIM   64
#define K_CODE  1024
#define MT      512           // tokens per block (grid = 128 -> single wave)
#define NTILES  128           // 1024 codes / 8 per mma tile
#define TAU     2e-3f

// Output layout (float32, tuple order)
#define OFF_ZQ   0
#define OFF_DIFF 4194304
#define OFF_IND  4194305
#define OFF_NEMB 4259841
#define OFF_NCS  4325377
#define OFF_NEA  4326401

// smem layout (byte offsets)
#define SM_B     0            // 1024 codes x 36 words (bf16(2w) padded)  147456 B
#define SM_WN    147456       // 1024 fp32                                  4096 B
#define SM_FIN   151552       // 512 int                                    2048 B
#define SM_DSUM  153600       // 16 fp32                                      64 B
#define SM_TOTAL 153664

__device__ float         g_wnorm[K_CODE];
__device__ double        g_diff_acc;
__device__ __nv_bfloat16 g_Bbf16[K_CODE * E_DIM];   // bf16(2*w), k-contiguous

__device__ __forceinline__ void mma16816(float* c, const uint32_t* a,
                                         uint32_t b0, uint32_t b1) {
    asm volatile(
        "mma.sync.aligned.m16n8k16.row.col.f32.bf16.bf16.f32 "
        "{%0,%1,%2,%3}, {%4,%5,%6,%7}, {%8,%9}, {%0,%1,%2,%3};"
        : "+f"(c[0]), "+f"(c[1]), "+f"(c[2]), "+f"(c[3])
        : "r"(a[0]), "r"(a[1]), "r"(a[2]), "r"(a[3]), "r"(b0), "r"(b1));
}

// Bit-exact reference distance. xn = sequential sum of fl(x_k^2);
// dot2 = sequential-k FMA chain of x*(2w); dist = fl( fl(xn - dot2) + wn ).
__device__ __noinline__ float exact_dist(const float* __restrict__ xr,
                                         const float* __restrict__ w,
                                         float wnj) {
    float xn = 0.f;
    #pragma unroll
    for (int k = 0; k < E_DIM; k++)
        xn = __fadd_rn(xn, __fmul_rn(xr[k], xr[k]));
    float acc = 0.f;
    #pragma unroll
    for (int k4 = 0; k4 < 16; k4++) {
        float4 wv = __ldg((const float4*)w + k4);
        acc = __fmaf_rn(xr[4 * k4 + 0], 2.f * wv.x, acc);
        acc = __fmaf_rn(xr[4 * k4 + 1], 2.f * wv.y, acc);
        acc = __fmaf_rn(xr[4 * k4 + 2], 2.f * wv.z, acc);
        acc = __fmaf_rn(xr[4 * k4 + 3], 2.f * wv.w, acc);
    }
    return __fadd_rn(__fsub_rn(xn, acc), wnj);
}

// ---------------------------------------------------------------------------
// k_prep: wnorm exact (reference order); B -> bf16(2w); seed EMA; zero diff
// ---------------------------------------------------------------------------
__global__ void k_prep(const float* __restrict__ embed,
                       const float* __restrict__ cluster,
                       const float* __restrict__ eavg,
                       float* __restrict__ out) {
    int t = blockIdx.x * blockDim.x + threadIdx.x;   // 65536
    out[OFF_NEA + t] = 0.99f * eavg[t];
    g_Bbf16[t] = __float2bfloat16_rn(2.f * embed[t]);
    if (t < K_CODE) {
        out[OFF_NCS + t] = 0.99f * cluster[t];
        const float* w = embed + (size_t)t * E_DIM;
        float s = 0.f;
        #pragma unroll
        for (int i = 0; i < E_DIM; i++)
            s = __fadd_rn(s, __fmul_rn(w[i], w[i]));
        g_wnorm[t] = s;
    }
    if (t == 0) g_diff_acc = 0.0;
}

// ---------------------------------------------------------------------------
// k_mma: single-pass bf16 mma.sync filter w/ self-compacting candidate buffer
//        + warp-granular redo fallback + exact fp32 verify + fused epilogue
// ---------------------------------------------------------------------------
__global__ void __launch_bounds__(512, 1)
k_mma(const float* __restrict__ z_e, const float* __restrict__ embed,
      float* __restrict__ out) {
    extern __shared__ char smem[];
    uint32_t* Bs   = (uint32_t*)(smem + SM_B);     // [code][36 words]
    float*    wns  = (float*)(smem + SM_WN);
    int*      fin  = (int*)(smem + SM_FIN);
    float*    dsum = (float*)(smem + SM_DSUM);

    const int tid  = threadIdx.x;                  // 512
    const int wid  = tid >> 5;                     // 16 warps
    const int lane = tid & 31;
    const int g    = lane >> 2;                    // 0..7
    const int t4   = lane & 3;                     // 0..3
    const int tbase = blockIdx.x * MT;

    // ---- stage B (8192 uint4) + wnorm ----
    {
        const uint4* src = (const uint4*)g_Bbf16;
        for (int i = tid; i < 8192; i += 512) {
            int n = i >> 3, w4 = (i & 7) << 2;
            *(uint4*)(Bs + n * 36 + w4) = src[i];
        }
    }
    for (int i = tid; i < K_CODE; i += 512) wns[i] = g_wnorm[i];
    __syncthreads();

    // ---- A fragments (bf16) directly from global z_e ----
    // slot q' = q + 2*mt : rows g, g+8 (mt0) / g+16, g+24 (mt1) within warp
    uint32_t A[2][4][4];
    const float* rp[4];
    int trow[4];
    #pragma unroll
    for (int mt = 0; mt < 2; mt++)
        #pragma unroll
        for (int q = 0; q < 2; q++) {
            int tl = wid * 32 + g + mt * 16 + q * 8;
            const float* xr = z_e + (size_t)(tbase + tl) * E_DIM;
            rp[q + 2 * mt] = xr;
            trow[q + 2 * mt] = tl;
            #pragma unroll
            for (int ks = 0; ks < 4; ks++)
                #pragma unroll
                for (int kh = 0; kh < 2; kh++) {
                    int kk = 2 * (t4 + 4 * kh + 8 * ks);
                    float2 v = *(const float2*)(xr + kk);
                    __nv_bfloat162 h = __floats2bfloat162_rn(v.x, v.y);
                    A[mt][ks][q + 2 * kh] = *(uint32_t*)&h;
                }
        }

    // ---- single-pass scan: running min + 3-slot self-compacting buffer ----
    float rm[4] = {FLT_MAX, FLT_MAX, FLT_MAX, FLT_MAX};
    float ss[4][3];
    int   js[4][3];
    #pragma unroll
    for (int q = 0; q < 4; q++)
        #pragma unroll
        for (int s = 0; s < 3; s++) { ss[q][s] = FLT_MAX; js[q][s] = 0; }
    unsigned ovf = 0;

    const uint32_t* bp = Bs + g * 36 + t4;

    #define PROC(q, cval, wnv, jv)                                            \
        do { float _s = (wnv) - (cval);                                       \
             rm[q] = fminf(rm[q], _s);                                        \
             if (_s <= rm[q] + TAU) {                                         \
                 float _rt = rm[q] + TAU;                                     \
                 if      (ss[q][0] > _rt) { ss[q][0] = _s; js[q][0] = (jv); } \
                 else if (ss[q][1] > _rt) { ss[q][1] = _s; js[q][1] = (jv); } \
                 else if (ss[q][2] > _rt) { ss[q][2] = _s; js[q][2] = (jv); } \
                 else ovf |= (1u << (q));                                     \
             } } while (0)

    #pragma unroll 1
    for (int nt = 0; nt < NTILES; nt++) {
        const uint32_t* bb = bp + nt * 288;
        float c0[4] = {0.f, 0.f, 0.f, 0.f};
        float c1[4] = {0.f, 0.f, 0.f, 0.f};
        #pragma unroll
        for (int ks = 0; ks < 4; ks++) {
            uint32_t b0 = bb[8 * ks];
            uint32_t b1 = bb[8 * ks + 4];
            mma16816(c0, A[0][ks], b0, b1);
            mma16816(c1, A[1][ks], b0, b1);
        }
        int   j0  = nt * 8 + 2 * t4;
        float wn0 = wns[j0], wn1 = wns[j0 + 1];
        PROC(0, c0[0], wn0, j0); PROC(0, c0[1], wn1, j0 + 1);
        PROC(1, c0[2], wn0, j0); PROC(1, c0[3], wn1, j0 + 1);
        PROC(2, c1[0], wn0, j0); PROC(2, c1[1], wn1, j0 + 1);
        PROC(3, c1[2], wn0, j0); PROC(3, c1[3], wn1, j0 + 1);
    }
    #undef PROC

    float bd[4] = {FLT_MAX, FLT_MAX, FLT_MAX, FLT_MAX};
    int   bi[4] = {0x7FFFFFFF, 0x7FFFFFFF, 0x7FFFFFFF, 0x7FFFFFFF};

    #define MERGE(q, d, j)                                                    \
        if ((d) < bd[q] || ((d) == bd[q] && (j) < bi[q])) { bd[q] = (d); bi[q] = (j); }

    // ---- warp-granular redo for overflowed (thread,q) slots (rare) ----
    if (__any_sync(0xffffffffu, ovf != 0)) {
        #define RCHK(q, cval, wnv, jv)                                        \
            do { if ((ovf >> (q)) & 1u) {                                     \
                 float _s = (wnv) - (cval);                                   \
                 if (_s <= rm[q] + TAU) {                                     \
                     float _d = exact_dist(rp[q],                             \
                                           embed + (size_t)(jv) * E_DIM,      \
                                           (wnv));                            \
                     MERGE(q, _d, (jv)); } } } while (0)
        #pragma unroll 1
        for (int nt = 0; nt < NTILES; nt++) {
            const uint32_t* bb = bp + nt * 288;
            float c0[4] = {0.f, 0.f, 0.f, 0.f};
            float c1[4] = {0.f, 0.f, 0.f, 0.f};
            #pragma unroll
            for (int ks = 0; ks < 4; ks++) {
                uint32_t b0 = bb[8 * ks];
                uint32_t b1 = bb[8 * ks + 4];
                mma16816(c0, A[0][ks], b0, b1);
                mma16816(c1, A[1][ks], b0, b1);
            }
            int   j0  = nt * 8 + 2 * t4;
            float wn0 = wns[j0], wn1 = wns[j0 + 1];
            RCHK(0, c0[0], wn0, j0); RCHK(0, c0[1], wn1, j0 + 1);
            RCHK(1, c0[2], wn0, j0); RCHK(1, c0[3], wn1, j0 + 1);
            RCHK(2, c1[0], wn0, j0); RCHK(2, c1[1], wn1, j0 + 1);
            RCHK(3, c1[2], wn0, j0); RCHK(3, c1[3], wn1, j0 + 1);
        }
        #undef RCHK
    }

    // ---- exact resolution of surviving buffered candidates ----
    #pragma unroll
    for (int q = 0; q < 4; q++) {
        if (!((ovf >> q) & 1u)) {
            float rt = rm[q] + TAU;
            #pragma unroll
            for (int s = 0; s < 3; s++) {
                if (ss[q][s] <= rt) {
                    int j = js[q][s];
                    float d = exact_dist(rp[q], embed + (size_t)j * E_DIM,
                                         wns[j]);
                    MERGE(q, d, j);
                }
            }
        }
    }
    #undef MERGE

    // ---- quad merge (lowest dist, then lowest index) + store ----
    #pragma unroll
    for (int q = 0; q < 4; q++) {
        float d = bd[q]; int j = bi[q];
        #pragma unroll
        for (int off = 1; off < 4; off <<= 1) {
            float od = __shfl_xor_sync(0xffffffffu, d, off);
            int   oj = __shfl_xor_sync(0xffffffffu, j, off);
            if (od < d || (od == d && oj < j)) { d = od; j = oj; }
        }
        if (t4 == 0) {
            int tl = trow[q];
            fin[tl] = j;
            out[OFF_IND + tbase + tl] = (float)j;
            atomicAdd(out + OFF_NCS + j, 0.01f);
        }
    }
    __syncthreads();

    // ---- fused epilogue: z_q_st + diff + EMA scatter (coalesced) ----
    float ldiff = 0.f;
    for (int i = tid; i < MT * E_DIM; i += 512) {
        int row = i >> 6, col = i & 63;
        int idx = fin[row];
        float z = z_e[(size_t)(tbase + row) * E_DIM + col];
        float w = __ldg(embed + (size_t)idx * E_DIM + col);
        float d = __fsub_rn(w, z);
        ldiff += d * d;
        out[OFF_ZQ + (size_t)(tbase + row) * E_DIM + col] = __fadd_rn(z, d);
        atomicAdd(out + OFF_NEA + (size_t)idx * E_DIM + col, 0.01f * z);
    }
    #pragma unroll
    for (int o = 16; o > 0; o >>= 1)
        ldiff += __shfl_down_sync(0xffffffffu, ldiff, o);
    if (lane == 0) dsum[wid] = ldiff;
    __syncthreads();
    if (tid == 0) {
        double s = 0.0;
        #pragma unroll
        for (int i = 0; i < 16; i++) s += (double)dsum[i];
        atomicAdd(&g_diff_acc, s);
    }
}

// ---------------------------------------------------------------------------
// k_final: n = sum(new_cluster_size); cs normalize; new_embed; diff
// ---------------------------------------------------------------------------
__global__ void k_final(float* __restrict__ out) {
    __shared__ float red[1024];
    int k = threadIdx.x;
    float c = out[OFF_NCS + k];
    red[k] = c;
    __syncthreads();
    for (int o = 512; o > 0; o >>= 1) {
        if (k < o) red[k] += red[k + o];
        __syncthreads();
    }
    float n = red[0];
    float cs = (c + 1e-5f) / (n + 1024.0f * 1e-5f) * n;
    const float* src = out + OFF_NEA  + (size_t)k * E_DIM;
    float*       dst = out + OFF_NEMB + (size_t)k * E_DIM;
    #pragma unroll
    for (int u = 0; u < E_DIM; u++) dst[u] = src[u] / cs;
    if (k == 0) out[OFF_DIFF] = (float)(g_diff_acc * (1.0 / 4194304.0));
}

// ---------------------------------------------------------------------------
extern "C" void kernel_launch(void* const* d_in, const int* in_sizes, int n_in,
                              void* d_out, int out_size) {
    const float* z_e     = (const float*)d_in[0];
    const float* embed   = (const float*)d_in[1];
    const float* cluster = (const float*)d_in[2];
    const float* eavg    = (const float*)d_in[3];
    float* out = (float*)d_out;

    int T = in_sizes[0] / E_DIM;     // 65536 tokens

    static int configured = 0;
    if (!configured) {
        cudaFuncSetAttribute(k_mma, cudaFuncAttributeMaxDynamicSharedMemorySize,
                             SM_TOTAL);
        configured = 1;
    }

    k_prep<<<512, 128>>>(embed, cluster, eavg, out);
    k_mma<<<T / MT, 512, SM_TOTAL>>>(z_e, embed, out);
    k_final<<<1, 1024>>>(out);
}

// round 9
// speedup vs baseline: 1.1630x; 1.1630x over previous
#include <cuda_runtime.h>
#include <cuda_bf16.h>
#include <cfloat>
#include <cstdint>

#define E_DIM   64
#define K_CODE  1024
#define MT      512           // tokens per block (grid = 128 -> single wave)
#define NTILES  128           // 1024 codes / 8 per mma tile
#define TAU     2e-3f
#define QCAP    12288

// Output layout (float32, tuple order)
#define OFF_ZQ   0
#define OFF_DIFF 4194304
#define OFF_IND  4194305
#define OFF_NEMB 4259841
#define OFF_NCS  4325377
#define OFF_NEA  4326401

// smem layout (byte offsets)
#define SM_B     0            // 1024 codes x 36 words (bf16(2w) padded) 147456 B
#define SM_WN    147456       // 1024 fp32                                 4096 B
#define SM_XN    151552       // 512 fp32 (exact xnorm per row)            2048 B
#define SM_RES   153600       // 512 u64  (packed dist|idx)                4096 B
#define SM_Q     157696       // QCAP uint32                              49152 B
#define SM_QCNT  206848       // int                                          4 B
#define SM_DSUM  206864       // 16 fp32                                     64 B
#define SM_TOTAL 206976

__device__ float         g_wnorm[K_CODE];
__device__ double        g_diff_acc;
__device__ __nv_bfloat16 g_Bbf16[K_CODE * E_DIM];   // bf16(2*w), k-contiguous

__device__ __forceinline__ void mma16816(float* c, const uint32_t* a,
                                         uint32_t b0, uint32_t b1) {
    asm volatile(
        "mma.sync.aligned.m16n8k16.row.col.f32.bf16.bf16.f32 "
        "{%0,%1,%2,%3}, {%4,%5,%6,%7}, {%8,%9}, {%0,%1,%2,%3};"
        : "+f"(c[0]), "+f"(c[1]), "+f"(c[2]), "+f"(c[3])
        : "r"(a[0]), "r"(a[1]), "r"(a[2]), "r"(a[3]), "r"(b0), "r"(b1));
}

// Bit-exact reference distance: dot2 = sequential-k FMA chain of x*(2w);
// dist = fl( fl(xn - dot2) + wn ).  xn precomputed in reference order.
__device__ __noinline__ float exact_dist(const float* __restrict__ xr,
                                         const float* __restrict__ w,
                                         float xn, float wnj) {
    float acc = 0.f;
    #pragma unroll
    for (int k4 = 0; k4 < 16; k4++) {
        float4 wv = __ldg((const float4*)w + k4);
        acc = __fmaf_rn(xr[4 * k4 + 0], 2.f * wv.x, acc);
        acc = __fmaf_rn(xr[4 * k4 + 1], 2.f * wv.y, acc);
        acc = __fmaf_rn(xr[4 * k4 + 2], 2.f * wv.z, acc);
        acc = __fmaf_rn(xr[4 * k4 + 3], 2.f * wv.w, acc);
    }
    return __fadd_rn(__fsub_rn(xn, acc), wnj);
}

// ---------------------------------------------------------------------------
// k_prep: wnorm exact (reference order); B -> bf16(2w); seed EMA; zero diff
// ---------------------------------------------------------------------------
__global__ void k_prep(const float* __restrict__ embed,
                       const float* __restrict__ cluster,
                       const float* __restrict__ eavg,
                       float* __restrict__ out) {
    int t = blockIdx.x * blockDim.x + threadIdx.x;   // 65536
    out[OFF_NEA + t] = 0.99f * eavg[t];
    g_Bbf16[t] = __float2bfloat16_rn(2.f * embed[t]);
    if (t < K_CODE) {
        out[OFF_NCS + t] = 0.99f * cluster[t];
        const float* w = embed + (size_t)t * E_DIM;
        float s = 0.f;
        #pragma unroll
        for (int i = 0; i < E_DIM; i++)
            s = __fadd_rn(s, __fmul_rn(w[i], w[i]));
        g_wnorm[t] = s;
    }
    if (t == 0) g_diff_acc = 0.0;
}

// ---------------------------------------------------------------------------
// k_mma: single-pass bf16 mma.sync filter + smem candidate queue +
//        parallel exact fp32 resolution via per-row u64 atomicMin
// ---------------------------------------------------------------------------
__global__ void __launch_bounds__(512, 1)
k_mma(const float* __restrict__ z_e, const float* __restrict__ embed,
      float* __restrict__ out) {
    extern __shared__ char smem[];
    uint32_t*           Bs   = (uint32_t*)(smem + SM_B);    // [code][36 words]
    float*              wns  = (float*)(smem + SM_WN);
    float*              xns  = (float*)(smem + SM_XN);
    unsigned long long* res  = (unsigned long long*)(smem + SM_RES);
    uint32_t*           que  = (uint32_t*)(smem + SM_Q);
    int*                qcnt = (int*)(smem + SM_QCNT);
    float*              dsum = (float*)(smem + SM_DSUM);

    const int tid  = threadIdx.x;                  // 512
    const int wid  = tid >> 5;                     // 16 warps
    const int lane = tid & 31;
    const int g    = lane >> 2;                    // 0..7
    const int t4   = lane & 3;                     // 0..3
    const int tbase = blockIdx.x * MT;

    // ---- stage B (8192 uint4), wnorm, per-row exact xnorm, init res/qcnt ----
    {
        const uint4* src = (const uint4*)g_Bbf16;
        for (int i = tid; i < 8192; i += 512) {
            int n = i >> 3, w4 = (i & 7) << 2;
            *(uint4*)(Bs + n * 36 + w4) = src[i];
        }
    }
    for (int i = tid; i < K_CODE; i += 512) wns[i] = g_wnorm[i];
    {   // one row per thread: xnorm in reference order; init result key
        const float* xr = z_e + (size_t)(tbase + tid) * E_DIM;
        float s = 0.f;
        #pragma unroll
        for (int k = 0; k < E_DIM; k++)
            s = __fadd_rn(s, __fmul_rn(xr[k], xr[k]));
        xns[tid] = s;
        res[tid] = ~0ull;
    }
    if (tid == 0) *qcnt = 0;
    __syncthreads();

    // ---- A fragments (bf16) directly from global z_e ----
    uint32_t A[2][4][4];
    int trow[4];
    #pragma unroll
    for (int mt = 0; mt < 2; mt++)
        #pragma unroll
        for (int q = 0; q < 2; q++) {
            int tl = wid * 32 + g + mt * 16 + q * 8;
            const float* xr = z_e + (size_t)(tbase + tl) * E_DIM;
            trow[q + 2 * mt] = tl;
            #pragma unroll
            for (int ks = 0; ks < 4; ks++)
                #pragma unroll
                for (int kh = 0; kh < 2; kh++) {
                    int kk = 2 * (t4 + 4 * kh + 8 * ks);
                    float2 v = *(const float2*)(xr + kk);
                    __nv_bfloat162 h = __floats2bfloat162_rn(v.x, v.y);
                    A[mt][ks][q + 2 * kh] = *(uint32_t*)&h;
                }
        }
    // accumulator slot mapping: c0[0,1]->trow[0], c0[2,3]->trow[1],
    //                           c1[0,1]->trow[2], c1[2,3]->trow[3]

    // ---- single-pass scan: running min + candidate push to smem queue ----
    float rm[4] = {FLT_MAX, FLT_MAX, FLT_MAX, FLT_MAX};
    const uint32_t* bp = Bs + g * 36 + t4;

    #define PUSH(row, j, wnj)                                                 \
        do { int _pos = atomicAdd(qcnt, 1);                                   \
             if (_pos < QCAP) que[_pos] = ((uint32_t)(row) << 10) | (j);      \
             else {                                                           \
                 float _d = exact_dist(z_e + (size_t)(tbase + (row)) * E_DIM, \
                                       embed + (size_t)(j) * E_DIM,           \
                                       xns[row], (wnj));                      \
                 unsigned long long _k =                                      \
                     ((unsigned long long)__float_as_uint(_d) << 32) |        \
                     (unsigned)(j);                                           \
                 atomicMin(&res[row], _k);                                    \
             } } while (0)

    #define PROC(q, s0, s1, j0v, wn0v, wn1v)                                  \
        do { rm[q] = fminf(rm[q], fminf((s0), (s1)));                         \
             float _rt = rm[q] + TAU;                                         \
             if ((s0) <= _rt) PUSH(trow[q], (j0v), (wn0v));                   \
             if ((s1) <= _rt) PUSH(trow[q], (j0v) + 1, (wn1v)); } while (0)

    #pragma unroll 1
    for (int nt = 0; nt < NTILES; nt++) {
        const uint32_t* bb = bp + nt * 288;
        float c0[4] = {0.f, 0.f, 0.f, 0.f};
        float c1[4] = {0.f, 0.f, 0.f, 0.f};
        #pragma unroll
        for (int ks = 0; ks < 4; ks++) {
            uint32_t b0 = bb[8 * ks];
            uint32_t b1 = bb[8 * ks + 4];
            mma16816(c0, A[0][ks], b0, b1);
            mma16816(c1, A[1][ks], b0, b1);
        }
        int   j0  = nt * 8 + 2 * t4;
        float wn0 = wns[j0], wn1 = wns[j0 + 1];
        PROC(0, wn0 - c0[0], wn1 - c0[1], j0, wn0, wn1);
        PROC(1, wn0 - c0[2], wn1 - c0[3], j0, wn0, wn1);
        PROC(2, wn0 - c1[0], wn1 - c1[1], j0, wn0, wn1);
        PROC(3, wn0 - c1[2], wn1 - c1[3], j0, wn0, wn1);
        if ((nt & 3) == 3) {   // quad-share running min (tighter filter)
            #pragma unroll
            for (int q = 0; q < 4; q++) {
                float v = rm[q];
                v = fminf(v, __shfl_xor_sync(0xffffffffu, v, 1));
                v = fminf(v, __shfl_xor_sync(0xffffffffu, v, 2));
                rm[q] = v;
            }
        }
    }
    #undef PROC
    #undef PUSH
    __syncthreads();

    // ---- parallel exact resolution of queued candidates ----
    {
        int n = *qcnt;
        if (n > QCAP) n = QCAP;
        for (int i = tid; i < n; i += 512) {
            uint32_t e = que[i];
            int row = e >> 10, j = e & 1023;
            float d = exact_dist(z_e + (size_t)(tbase + row) * E_DIM,
                                 embed + (size_t)j * E_DIM, xns[row], wns[j]);
            unsigned long long k =
                ((unsigned long long)__float_as_uint(d) << 32) | (unsigned)j;
            atomicMin(&res[row], k);
        }
    }
    __syncthreads();

    // ---- per-row finalize (thread = row) ----
    {
        int j = (int)(res[tid] & 0xffffffffull);
        out[OFF_IND + tbase + tid] = (float)j;
        atomicAdd(out + OFF_NCS + j, 0.01f);
    }

    // ---- fused epilogue: z_q_st + diff + EMA scatter (coalesced) ----
    float ldiff = 0.f;
    for (int i = tid; i < MT * E_DIM; i += 512) {
        int row = i >> 6, col = i & 63;
        int idx = (int)(res[row] & 0xffffffffull);
        float z = z_e[(size_t)(tbase + row) * E_DIM + col];
        float w = __ldg(embed + (size_t)idx * E_DIM + col);
        float d = __fsub_rn(w, z);
        ldiff += d * d;
        out[OFF_ZQ + (size_t)(tbase + row) * E_DIM + col] = __fadd_rn(z, d);
        atomicAdd(out + OFF_NEA + (size_t)idx * E_DIM + col, 0.01f * z);
    }
    #pragma unroll
    for (int o = 16; o > 0; o >>= 1)
        ldiff += __shfl_down_sync(0xffffffffu, ldiff, o);
    if (lane == 0) dsum[wid] = ldiff;
    __syncthreads();
    if (tid == 0) {
        double s = 0.0;
        #pragma unroll
        for (int i = 0; i < 16; i++) s += (double)dsum[i];
        atomicAdd(&g_diff_acc, s);
    }
}

// ---------------------------------------------------------------------------
// k_final: n = sum(new_cluster_size); cs normalize; new_embed; diff
// ---------------------------------------------------------------------------
__global__ void k_final(float* __restrict__ out) {
    __shared__ float red[1024];
    int k = threadIdx.x;
    float c = out[OFF_NCS + k];
    red[k] = c;
    __syncthreads();
    for (int o = 512; o > 0; o >>= 1) {
        if (k < o) red[k] += red[k + o];
        __syncthreads();
    }
    float n = red[0];
    float cs = (c + 1e-5f) / (n + 1024.0f * 1e-5f) * n;
    const float* src = out + OFF_NEA  + (size_t)k * E_DIM;
    float*       dst = out + OFF_NEMB + (size_t)k * E_DIM;
    #pragma unroll
    for (int u = 0; u < E_DIM; u++) dst[u] = src[u] / cs;
    if (k == 0) out[OFF_DIFF] = (float)(g_diff_acc * (1.0 / 4194304.0));
}

// ---------------------------------------------------------------------------
extern "C" void kernel_launch(void* const* d_in, const int* in_sizes, int n_in,
                              void* d_out, int out_size) {
    const float* z_e     = (const float*)d_in[0];
    const float* embed   = (const float*)d_in[1];
    const float* cluster = (const float*)d_in[2];
    const float* eavg    = (const float*)d_in[3];
    float* out = (float*)d_out;

    int T = in_sizes[0] / E_DIM;     // 65536 tokens

    static int configured = 0;
    if (!configured) {
        cudaFuncSetAttribute(k_mma, cudaFuncAttributeMaxDynamicSharedMemorySize,
                             SM_TOTAL);
        configured = 1;
    }

    k_prep<<<512, 128>>>(embed, cluster, eavg, out);
    k_mma<<<T / MT, 512, SM_TOTAL>>>(z_e, embed, out);
    k_final<<<1, 1024>>>(out);
}

// round 10
// speedup vs baseline: 1.5204x; 1.3073x over previous
#include <cuda_runtime.h>
#include <cuda_bf16.h>
#include <cfloat>
#include <cstdint>

#define E_DIM   64
#define K_CODE  1024
#define MT      512           // tokens per block (grid = 128 -> single wave)
#define NTILES  128           // 1024 codes / 8 per mma tile
#define TAU     2e-3f
#define WQCAP   768           // per-warp queue capacity (expect ~290)

// Output layout (float32, tuple order)
#define OFF_ZQ   0
#define OFF_DIFF 4194304
#define OFF_IND  4194305
#define OFF_NEMB 4259841
#define OFF_NCS  4325377
#define OFF_NEA  4326401

// smem layout (byte offsets)
#define SM_B     0            // 1024 codes x 36 words (bf16(2w) padded) 147456 B
#define SM_WN    147456       // 1024 fp32                                 4096 B
#define SM_XN    151552       // 512 fp32 (exact xnorm per row)            2048 B
#define SM_RES   153600       // 512 u64  (packed dist|idx)                4096 B
#define SM_Q     157696       // 16 x WQCAP uint32                        49152 B
#define SM_QCNT  206848       // 16 int                                      64 B
#define SM_DSUM  206912       // 16 fp32                                     64 B
#define SM_TOTAL 206976

__device__ float         g_wnorm[K_CODE];
__device__ double        g_diff_acc;
__device__ __nv_bfloat16 g_Bbf16[K_CODE * E_DIM];   // bf16(2*w), k-contiguous

__device__ __forceinline__ void mma16816(float* c, const uint32_t* a,
                                         uint32_t b0, uint32_t b1) {
    asm volatile(
        "mma.sync.aligned.m16n8k16.row.col.f32.bf16.bf16.f32 "
        "{%0,%1,%2,%3}, {%4,%5,%6,%7}, {%8,%9}, {%0,%1,%2,%3};"
        : "+f"(c[0]), "+f"(c[1]), "+f"(c[2]), "+f"(c[3])
        : "r"(a[0]), "r"(a[1]), "r"(a[2]), "r"(a[3]), "r"(b0), "r"(b1));
}

// Bit-exact reference distance: dot2 = sequential-k FMA chain of x*(2w);
// dist = fl( fl(xn - dot2) + wn ).  xn precomputed in reference order.
__device__ __noinline__ float exact_dist(const float* __restrict__ xr,
                                         const float* __restrict__ w,
                                         float xn, float wnj) {
    float acc = 0.f;
    #pragma unroll
    for (int k4 = 0; k4 < 16; k4++) {
        float4 wv = __ldg((const float4*)w + k4);
        acc = __fmaf_rn(xr[4 * k4 + 0], 2.f * wv.x, acc);
        acc = __fmaf_rn(xr[4 * k4 + 1], 2.f * wv.y, acc);
        acc = __fmaf_rn(xr[4 * k4 + 2], 2.f * wv.z, acc);
        acc = __fmaf_rn(xr[4 * k4 + 3], 2.f * wv.w, acc);
    }
    return __fadd_rn(__fsub_rn(xn, acc), wnj);
}

// ---------------------------------------------------------------------------
// k_prep: wnorm exact (reference order); B -> bf16(2w); seed EMA; zero diff
// ---------------------------------------------------------------------------
__global__ void k_prep(const float* __restrict__ embed,
                       const float* __restrict__ cluster,
                       const float* __restrict__ eavg,
                       float* __restrict__ out) {
    int t = blockIdx.x * blockDim.x + threadIdx.x;   // 65536
    out[OFF_NEA + t] = 0.99f * eavg[t];
    g_Bbf16[t] = __float2bfloat16_rn(2.f * embed[t]);
    if (t < K_CODE) {
        out[OFF_NCS + t] = 0.99f * cluster[t];
        const float* w = embed + (size_t)t * E_DIM;
        float s = 0.f;
        #pragma unroll
        for (int i = 0; i < E_DIM; i++)
            s = __fadd_rn(s, __fmul_rn(w[i], w[i]));
        g_wnorm[t] = s;
    }
    if (t == 0) g_diff_acc = 0.0;
}

// ---------------------------------------------------------------------------
// k_mma: single-pass bf16 mma.sync filter; ballot-compacted per-warp queues
//        (no atomics in scan); parallel exact fp32 drain via u64 atomicMin
// ---------------------------------------------------------------------------
__global__ void __launch_bounds__(512, 1)
k_mma(const float* __restrict__ z_e, const float* __restrict__ embed,
      float* __restrict__ out) {
    extern __shared__ char smem[];
    uint32_t*           Bs   = (uint32_t*)(smem + SM_B);    // [code][36 words]
    float*              wns  = (float*)(smem + SM_WN);
    float*              xns  = (float*)(smem + SM_XN);
    unsigned long long* res  = (unsigned long long*)(smem + SM_RES);
    uint32_t*           que  = (uint32_t*)(smem + SM_Q);    // [16][WQCAP]
    int*                qcnt = (int*)(smem + SM_QCNT);      // [16]
    float*              dsum = (float*)(smem + SM_DSUM);

    const int tid  = threadIdx.x;                  // 512
    const int wid  = tid >> 5;                     // 16 warps
    const int lane = tid & 31;
    const int g    = lane >> 2;                    // 0..7
    const int t4   = lane & 3;                     // 0..3
    const int tbase = blockIdx.x * MT;
    const uint32_t lmask = (1u << lane) - 1u;

    // ---- stage B (8192 uint4), wnorm, per-row exact xnorm, init res ----
    {
        const uint4* src = (const uint4*)g_Bbf16;
        for (int i = tid; i < 8192; i += 512) {
            int n = i >> 3, w4 = (i & 7) << 2;
            *(uint4*)(Bs + n * 36 + w4) = src[i];
        }
    }
    for (int i = tid; i < K_CODE; i += 512) wns[i] = g_wnorm[i];
    {
        const float* xr = z_e + (size_t)(tbase + tid) * E_DIM;
        float s = 0.f;
        #pragma unroll
        for (int k = 0; k < E_DIM; k++)
            s = __fadd_rn(s, __fmul_rn(xr[k], xr[k]));
        xns[tid] = s;
        res[tid] = ~0ull;
    }
    __syncthreads();

    // ---- A fragments (bf16) directly from global z_e ----
    uint32_t A[2][4][4];
    int trow[4];
    #pragma unroll
    for (int mt = 0; mt < 2; mt++)
        #pragma unroll
        for (int q = 0; q < 2; q++) {
            int tl = wid * 32 + g + mt * 16 + q * 8;
            const float* xr = z_e + (size_t)(tbase + tl) * E_DIM;
            trow[q + 2 * mt] = tl;
            #pragma unroll
            for (int ks = 0; ks < 4; ks++)
                #pragma unroll
                for (int kh = 0; kh < 2; kh++) {
                    int kk = 2 * (t4 + 4 * kh + 8 * ks);
                    float2 v = *(const float2*)(xr + kk);
                    __nv_bfloat162 h = __floats2bfloat162_rn(v.x, v.y);
                    A[mt][ks][q + 2 * kh] = *(uint32_t*)&h;
                }
        }

    // ---- single-pass scan; ballot-compacted pushes, no atomics ----
    float rm[4] = {FLT_MAX, FLT_MAX, FLT_MAX, FLT_MAX};
    int wq = 0;                                   // per-warp queue count (uniform)
    uint32_t* myq = que + wid * WQCAP;
    const uint32_t* bp = Bs + g * 36 + t4;

    // ballot push: all lanes participate; pred lanes append compacted
    #define BPUSH(pred, row, j, wnv, sv)                                      \
        do { uint32_t _m = __ballot_sync(0xffffffffu, (pred));                \
             if (_m) {                                                        \
                 int _pos = wq + __popc(_m & lmask);                          \
                 if (pred) {                                                  \
                     if (_pos < WQCAP)                                        \
                         myq[_pos] = ((uint32_t)(row) << 10) | (j);           \
                     else {                                                   \
                         float _d = exact_dist(                               \
                             z_e + (size_t)(tbase + (row)) * E_DIM,           \
                             embed + (size_t)(j) * E_DIM, xns[row], (wnv));   \
                         unsigned long long _k =                              \
                             ((unsigned long long)__float_as_uint(_d) << 32)  \
                             | (unsigned)(j);                                 \
                         atomicMin(&res[row], _k);                            \
                     }                                                        \
                 }                                                            \
                 wq += __popc(_m);                                            \
             } } while (0)

    #define PROC(q, s0, s1, j0v, wn0v, wn1v)                                  \
        do { rm[q] = fminf(rm[q], fminf((s0), (s1)));                         \
             float _rt = rm[q] + TAU;                                         \
             BPUSH((s0) <= _rt, trow[q], (j0v), (wn0v), (s0));                \
             BPUSH((s1) <= _rt, trow[q], (j0v) + 1, (wn1v), (s1)); } while (0)

    #pragma unroll 1
    for (int nt = 0; nt < NTILES; nt++) {
        const uint32_t* bb = bp + nt * 288;
        float c0[4] = {0.f, 0.f, 0.f, 0.f};
        float c1[4] = {0.f, 0.f, 0.f, 0.f};
        #pragma unroll
        for (int ks = 0; ks < 4; ks++) {
            uint32_t b0 = bb[8 * ks];
            uint32_t b1 = bb[8 * ks + 4];
            mma16816(c0, A[0][ks], b0, b1);
            mma16816(c1, A[1][ks], b0, b1);
        }
        int   j0  = nt * 8 + 2 * t4;
        float wn0 = wns[j0], wn1 = wns[j0 + 1];
        PROC(0, wn0 - c0[0], wn1 - c0[1], j0, wn0, wn1);
        PROC(1, wn0 - c0[2], wn1 - c0[3], j0, wn0, wn1);
        PROC(2, wn0 - c1[0], wn1 - c1[1], j0, wn0, wn1);
        PROC(3, wn0 - c1[2], wn1 - c1[3], j0, wn0, wn1);
        if ((nt & 3) == 3) {   // quad-share running min (tighter filter)
            #pragma unroll
            for (int q = 0; q < 4; q++) {
                float v = rm[q];
                v = fminf(v, __shfl_xor_sync(0xffffffffu, v, 1));
                v = fminf(v, __shfl_xor_sync(0xffffffffu, v, 2));
                rm[q] = v;
            }
        }
    }
    #undef PROC
    #undef BPUSH

    if (lane == 0) qcnt[wid] = (wq < WQCAP) ? wq : WQCAP;
    __syncthreads();

    // ---- parallel exact drain of all 16 queues (convergent) ----
    #pragma unroll 1
    for (int w = 0; w < 16; w++) {
        int n = qcnt[w];
        const uint32_t* qq = que + w * WQCAP;
        for (int i = tid; i < n; i += 512) {
            uint32_t e = qq[i];
            int row = e >> 10, j = e & 1023;
            float d = exact_dist(z_e + (size_t)(tbase + row) * E_DIM,
                                 embed + (size_t)j * E_DIM, xns[row], wns[j]);
            unsigned long long k =
                ((unsigned long long)__float_as_uint(d) << 32) | (unsigned)j;
            atomicMin(&res[row], k);
        }
    }
    __syncthreads();

    // ---- per-row finalize (thread = row) ----
    {
        int j = (int)(res[tid] & 0xffffffffull);
        out[OFF_IND + tbase + tid] = (float)j;
        atomicAdd(out + OFF_NCS + j, 0.01f);
    }

    // ---- fused epilogue: z_q_st + diff + EMA scatter (coalesced) ----
    float ldiff = 0.f;
    for (int i = tid; i < MT * E_DIM; i += 512) {
        int row = i >> 6, col = i & 63;
        int idx = (int)(res[row] & 0xffffffffull);
        float z = z_e[(size_t)(tbase + row) * E_DIM + col];
        float w = __ldg(embed + (size_t)idx * E_DIM + col);
        float d = __fsub_rn(w, z);
        ldiff += d * d;
        out[OFF_ZQ + (size_t)(tbase + row) * E_DIM + col] = __fadd_rn(z, d);
        atomicAdd(out + OFF_NEA + (size_t)idx * E_DIM + col, 0.01f * z);
    }
    #pragma unroll
    for (int o = 16; o > 0; o >>= 1)
        ldiff += __shfl_down_sync(0xffffffffu, ldiff, o);
    if (lane == 0) dsum[wid] = ldiff;
    __syncthreads();
    if (tid == 0) {
        double s = 0.0;
        #pragma unroll
        for (int i = 0; i < 16; i++) s += (double)dsum[i];
        atomicAdd(&g_diff_acc, s);
    }
}

// ---------------------------------------------------------------------------
// k_final: n = sum(new_cluster_size); cs normalize; new_embed; diff
// ---------------------------------------------------------------------------
__global__ void k_final(float* __restrict__ out) {
    __shared__ float red[1024];
    int k = threadIdx.x;
    float c = out[OFF_NCS + k];
    red[k] = c;
    __syncthreads();
    for (int o = 512; o > 0; o >>= 1) {
        if (k < o) red[k] += red[k + o];
        __syncthreads();
    }
    float n = red[0];
    float cs = (c + 1e-5f) / (n + 1024.0f * 1e-5f) * n;
    const float* src = out + OFF_NEA  + (size_t)k * E_DIM;
    float*       dst = out + OFF_NEMB + (size_t)k * E_DIM;
    #pragma unroll
    for (int u = 0; u < E_DIM; u++) dst[u] = src[u] / cs;
    if (k == 0) out[OFF_DIFF] = (float)(g_diff_acc * (1.0 / 4194304.0));
}

// ---------------------------------------------------------------------------
extern "C" void kernel_launch(void* const* d_in, const int* in_sizes, int n_in,
                              void* d_out, int out_size) {
    const float* z_e     = (const float*)d_in[0];
    const float* embed   = (const float*)d_in[1];
    const float* cluster = (const float*)d_in[2];
    const float* eavg    = (const float*)d_in[3];
    float* out = (float*)d_out;

    int T = in_sizes[0] / E_DIM;     // 65536 tokens

    static int configured = 0;
    if (!configured) {
        cudaFuncSetAttribute(k_mma, cudaFuncAttributeMaxDynamicSharedMemorySize,
                             SM_TOTAL);
        configured = 1;
    }

    k_prep<<<512, 128>>>(embed, cluster, eavg, out);
    k_mma<<<T / MT, 512, SM_TOTAL>>>(z_e, embed, out);
    k_final<<<1, 1024>>>(out);
}